// round 15
// baseline (speedup 1.0000x reference)
#include <cuda_runtime.h>
#include <cuda_fp16.h>
#include <cuda_bf16.h>

#define NU 100000
#define NI 50000
#define NT 150000          // NU + NI
#define EE 4000000
#define DD 64
#define BB 4096

#define SCAN_B 1024
#define NBLK_SCAN ((NT + SCAN_B - 1) / SCAN_B)   // 147 (all co-resident on 148 SMs)

#define TB 256
#define HIST_BLOCKS ((EE / 8 + TB - 1) / TB)      // 1954 (8 edges/thread)
#define FILL_BLOCKS ((EE / 4 + TB - 1) / TB)      // 3907 (4 edges/thread)
#define INIT_BLOCKS ((NT * 16 + TB - 1) / TB)     // 9375
// interleave: groups of 10 blocks = 3 fill + 7 init  (3907:9375 ~ 1:2.4)
#define GROUPS 1340                                // 3*1340=4020>=3907, 7*1340=9380>=9375
#define MIX_BLOCKS (GROUPS * 10)

// ---- scratch (device globals: allocation-free) ----
__device__ __align__(256) __half g_m0[NT * DD];   // fp16 scaled mirrors (m0 = dis*e0, m_{k+1} = dis^2*S)
__device__ __align__(256) __half g_m1[NT * DD];
__device__ __align__(256) __half g_m2[NT * DD];
__device__ __align__(256) float  g_dis[NT];       // d^{-1/2}
__device__ __align__(256) float  g_dsq[NT];       // d^{+1/2}  (0 if deg==0)
__device__ __align__(256) int    g_deg[NT];
__device__ __align__(256) int    g_rowptr[NT + 1]; // FINAL rowptr (single-pass scan)
__device__ __align__(256) int    g_scanflag[NBLK_SCAN + 1]; // lookback: prefix+1, 0=not ready
__device__ __align__(256) unsigned short g_pos[EE]; // per-edge within-row index (from hist)
__device__ __align__(256) int    g_col[EE];       // CSR columns

__device__ __forceinline__ int2 pack_half4(float4 s) {
    __half2 p0 = __floats2half2_rn(s.x, s.y);
    __half2 p1 = __floats2half2_rn(s.z, s.w);
    return make_int2(*reinterpret_cast<int*>(&p0), *reinterpret_cast<int*>(&p1));
}

// histogram of edge rows, 8 edges/thread; records each edge's within-row slot
__global__ void __launch_bounds__(256) k_hist(const int4* __restrict__ row4) {
    int i = (blockIdx.x * blockDim.x + threadIdx.x) * 2;   // int4 index (even)
    if (i < EE / 4) {
        int4 r0 = __ldg(&row4[i]);
        int4 r1 = __ldg(&row4[i + 1]);
        unsigned p0 = atomicAdd(&g_deg[r0.x], 1);
        unsigned p1 = atomicAdd(&g_deg[r0.y], 1);
        unsigned p2 = atomicAdd(&g_deg[r0.z], 1);
        unsigned p3 = atomicAdd(&g_deg[r0.w], 1);
        unsigned p4 = atomicAdd(&g_deg[r1.x], 1);
        unsigned p5 = atomicAdd(&g_deg[r1.y], 1);
        unsigned p6 = atomicAdd(&g_deg[r1.z], 1);
        unsigned p7 = atomicAdd(&g_deg[r1.w], 1);
        uint4 pk;
        pk.x = (p0 & 0xFFFF) | (p1 << 16);
        pk.y = (p2 & 0xFFFF) | (p3 << 16);
        pk.z = (p4 & 0xFFFF) | (p5 << 16);
        pk.w = (p6 & 0xFFFF) | (p7 << 16);
        *reinterpret_cast<uint4*>(&g_pos[i * 4]) = pk;     // 16B aligned: i even
    }
}

// Single-pass scan with decoupled lookback (147 blocks, all resident).
// Writes FINAL exclusive rowptr + dis/dsq.
__global__ void __launch_bounds__(SCAN_B) k_scan() {
    __shared__ int sh[SCAN_B];
    __shared__ int sh_prefix;
    int b = blockIdx.x;
    int i = b * SCAN_B + threadIdx.x;
    int v = (i < NT) ? g_deg[i] : 0;
    if (i < NT) {
        g_dis[i] = (v > 0) ? rsqrtf((float)v) : 0.0f;
        g_dsq[i] = (v > 0) ? sqrtf((float)v)  : 0.0f;
    }
    sh[threadIdx.x] = v;
    __syncthreads();
    for (int off = 1; off < SCAN_B; off <<= 1) {
        int x = (threadIdx.x >= off) ? sh[threadIdx.x - off] : 0;
        __syncthreads();
        sh[threadIdx.x] += x;
        __syncthreads();
    }
    int incl = sh[threadIdx.x];

    if (threadIdx.x == 0) {
        int prefix = 0;
        if (b > 0) {
            int f;
            while ((f = *((volatile int*)&g_scanflag[b])) == 0) { }
            prefix = f - 1;
        }
        sh_prefix = prefix;
        int total = prefix + sh[SCAN_B - 1];
        *((volatile int*)&g_scanflag[b + 1]) = total + 1;  // single-word publish
    }
    __syncthreads();
    int prefix = sh_prefix;
    if (i < NT) g_rowptr[i] = prefix + incl - v;
    if (i == NT - 1) g_rowptr[NT] = EE;
}

// Fused atomic-FREE CSR fill + m0-init, roles interleaved (3 fill : 7 init).
__global__ void __launch_bounds__(256) k_fill_init(
        const int4* __restrict__ row4, const int4* __restrict__ col4,
        const float4* __restrict__ users, const float4* __restrict__ items) {
    int b = blockIdx.x;
    int g = b / 10;
    int k = b % 10;
    if (k < 3) {
        // ---- fill role: 4 edges/thread ----
        int fb = g * 3 + k;
        if (fb >= FILL_BLOCKS) return;
        int i = fb * blockDim.x + threadIdx.x;             // int4 index
        if (i < EE / 4) {
            int4 r = __ldg(&row4[i]);
            int4 c = __ldg(&col4[i]);
            uint2 pk = *reinterpret_cast<const uint2*>(&g_pos[i * 4]);
            int p0 = __ldg(&g_rowptr[r.x]) + (pk.x & 0xFFFF);
            int p1 = __ldg(&g_rowptr[r.y]) + (pk.x >> 16);
            int p2 = __ldg(&g_rowptr[r.z]) + (pk.y & 0xFFFF);
            int p3 = __ldg(&g_rowptr[r.w]) + (pk.y >> 16);
            g_col[p0] = c.x;
            g_col[p1] = c.y;
            g_col[p2] = c.z;
            g_col[p3] = c.w;
        }
    } else {
        // ---- init role ----
        int ib = g * 7 + (k - 3);
        if (ib >= INIT_BLOCKS) return;
        int i = ib * blockDim.x + threadIdx.x;             // over NT*16
        if (i < NT * 16) {
            int node = i >> 4;
            float d = g_dis[node];
            float4 x = (node < NU) ? __ldg(&users[i])
                                   : __ldg(&items[i - NU * 16]);
            reinterpret_cast<int2*>(g_m0)[i] =
                pack_half4(make_float4(d * x.x, d * x.y, d * x.z, d * x.w));
        }
    }
}

// CSR SpMM: 16 threads/row, int2 (8B) per lane; unweighted segment-sum of
// scaled fp16 mirrors. Stores next scaled mirror: m_{k+1} = dis[r]^2 * S.
__global__ void __launch_bounds__(256) k_spmm(int hop) {
    int t = blockIdx.x * blockDim.x + threadIdx.x;
    int r = t >> 4;
    if (r >= NT) return;
    int lane = t & 15;

    const int2* __restrict__ srcm = (hop == 0) ? (const int2*)g_m0 : (const int2*)g_m1;
    int2* dstm                    = (hop == 0) ? (int2*)g_m1       : (int2*)g_m2;

    int beg = g_rowptr[r];
    int end = g_rowptr[r + 1];
    const int* __restrict__ col = g_col;

    float4 s = make_float4(0.f, 0.f, 0.f, 0.f);
    int i = beg;
    for (; i + 3 < end; i += 4) {
        int c0 = __ldg(&col[i]);
        int c1 = __ldg(&col[i + 1]);
        int c2 = __ldg(&col[i + 2]);
        int c3 = __ldg(&col[i + 3]);
        int2 u0 = __ldg(&srcm[c0 * 16 + lane]);
        int2 u1 = __ldg(&srcm[c1 * 16 + lane]);
        int2 u2 = __ldg(&srcm[c2 * 16 + lane]);
        int2 u3 = __ldg(&srcm[c3 * 16 + lane]);
        float2 a0 = __half22float2(*reinterpret_cast<__half2*>(&u0.x));
        float2 b0 = __half22float2(*reinterpret_cast<__half2*>(&u0.y));
        float2 a1 = __half22float2(*reinterpret_cast<__half2*>(&u1.x));
        float2 b1 = __half22float2(*reinterpret_cast<__half2*>(&u1.y));
        float2 a2 = __half22float2(*reinterpret_cast<__half2*>(&u2.x));
        float2 b2 = __half22float2(*reinterpret_cast<__half2*>(&u2.y));
        float2 a3 = __half22float2(*reinterpret_cast<__half2*>(&u3.x));
        float2 b3 = __half22float2(*reinterpret_cast<__half2*>(&u3.y));
        s.x += (a0.x + a1.x) + (a2.x + a3.x);
        s.y += (a0.y + a1.y) + (a2.y + a3.y);
        s.z += (b0.x + b1.x) + (b2.x + b3.x);
        s.w += (b0.y + b1.y) + (b2.y + b3.y);
    }
    for (; i < end; i++) {
        int c = __ldg(&col[i]);
        int2 u = __ldg(&srcm[c * 16 + lane]);
        float2 a = __half22float2(*reinterpret_cast<__half2*>(&u.x));
        float2 b = __half22float2(*reinterpret_cast<__half2*>(&u.y));
        s.x += a.x; s.y += a.y; s.z += b.x; s.w += b.y;
    }

    float dr = g_dis[r];
    float f = dr * dr;
    dstm[r * 16 + lane] =
        pack_half4(make_float4(f * s.x, f * s.y, f * s.z, f * s.w));
}

// Fused hop-3 + gather: one warp per output slot (b, side).
// S = sum_{c in N(r)} m2[c];  out = 0.25*(e0[r] + dsq*(m1[r]+m2[r]) + dis[r]*S)
__global__ void __launch_bounds__(256) k_gather_fused(
        const float* __restrict__ users, const float* __restrict__ items,
        const int* __restrict__ uid, const int* __restrict__ iid,
        float2* __restrict__ out) {
    int t = blockIdx.x * blockDim.x + threadIdx.x;
    int slot = t >> 5;                 // 8192 slots
    if (slot >= BB * 2) return;
    int lane = t & 31;
    int b = slot >> 1, side = slot & 1;

    int node;
    const float2* e0;
    if (!side) { int u = __ldg(&uid[b]); node = u;      e0 = (const float2*)users + u * 32; }
    else       { int v = __ldg(&iid[b]); node = NU + v; e0 = (const float2*)items + v * 32; }

    int beg = g_rowptr[node];
    int end = g_rowptr[node + 1];
    const int* __restrict__ col = g_col;
    const __half2* __restrict__ m2h = (const __half2*)g_m2;

    float2 S = make_float2(0.f, 0.f);
    int i = beg;
    for (; i + 3 < end; i += 4) {
        int c0 = __ldg(&col[i]);
        int c1 = __ldg(&col[i + 1]);
        int c2 = __ldg(&col[i + 2]);
        int c3 = __ldg(&col[i + 3]);
        float2 x0 = __half22float2(__ldg(&m2h[c0 * 32 + lane]));
        float2 x1 = __half22float2(__ldg(&m2h[c1 * 32 + lane]));
        float2 x2 = __half22float2(__ldg(&m2h[c2 * 32 + lane]));
        float2 x3 = __half22float2(__ldg(&m2h[c3 * 32 + lane]));
        S.x += (x0.x + x1.x) + (x2.x + x3.x);
        S.y += (x0.y + x1.y) + (x2.y + x3.y);
    }
    for (; i < end; i++) {
        int c = __ldg(&col[i]);
        float2 x = __half22float2(__ldg(&m2h[c * 32 + lane]));
        S.x += x.x; S.y += x.y;
    }

    float dr = g_dis[node];
    float dq = g_dsq[node];
    float2 v0 = __ldg(&e0[lane]);
    float2 a1 = __half22float2(((const __half2*)g_m1)[node * 32 + lane]);
    float2 a2 = __half22float2(((const __half2*)g_m2)[node * 32 + lane]);

    float2 o;
    o.x = 0.25f * (v0.x + dq * (a1.x + a2.x) + dr * S.x);
    o.y = 0.25f * (v0.y + dq * (a1.y + a2.y) + dr * S.y);
    out[slot * 32 + lane] = o;         // = b*64 + side*32 + lane
}

extern "C" void kernel_launch(void* const* d_in, const int* in_sizes, int n_in,
                              void* d_out, int out_size) {
    const float* users = (const float*)d_in[0];
    const float* items = (const float*)d_in[1];
    const int*   erow  = (const int*)d_in[2];
    const int*   ecol  = (const int*)d_in[3];
    const int*   uid   = (const int*)d_in[4];
    const int*   iid   = (const int*)d_in[5];
    float2*      out   = (float2*)d_out;

    void* degp = nullptr;
    cudaGetSymbolAddress(&degp, g_deg);
    cudaMemsetAsync(degp, 0, NT * sizeof(int));
    void* flagp = nullptr;
    cudaGetSymbolAddress(&flagp, g_scanflag);
    cudaMemsetAsync(flagp, 0, (NBLK_SCAN + 1) * sizeof(int));

    k_hist  <<<HIST_BLOCKS, TB>>>((const int4*)erow);
    k_scan  <<<NBLK_SCAN, SCAN_B>>>();
    k_fill_init<<<MIX_BLOCKS, TB>>>(
        (const int4*)erow, (const int4*)ecol,
        (const float4*)users, (const float4*)items);

    int spmm_threads = NT * 16;
    k_spmm<<<(spmm_threads + TB - 1) / TB, TB>>>(0);
    k_spmm<<<(spmm_threads + TB - 1) / TB, TB>>>(1);

    k_gather_fused<<<(BB * 2 * 32 + TB - 1) / TB, TB>>>(users, items, uid, iid, out);
}

// round 16
// speedup vs baseline: 1.2494x; 1.2494x over previous
#include <cuda_runtime.h>
#include <cuda_fp16.h>
#include <cuda_bf16.h>

#define NU 100000
#define NI 50000
#define NT 150000          // NU + NI
#define EE 4000000
#define DD 64
#define BB 4096

#define SCAN_B 1024
#define NBLK_SCAN ((NT + SCAN_B - 1) / SCAN_B)   // 147

#define TB 256
#define HIST_BLOCKS ((EE / 8 + TB - 1) / TB)      // 1954 (8 edges/thread)
#define FILL_BLOCKS ((EE / 4 + TB - 1) / TB)      // 3907 (4 edges/thread)
#define INIT_BLOCKS ((NT * 16 + TB - 1) / TB)     // 9375
// interleave: groups of 10 blocks = 3 fill + 7 init  (3907:9375 ~ 1:2.4)
#define GROUPS 1340                                // 3*1340=4020>=3907, 7*1340=9380>=9375
#define MIX_BLOCKS (GROUPS * 10)

// ---- scratch (device globals: allocation-free) ----
__device__ __align__(256) __half g_m0[NT * DD];   // fp16 scaled mirrors (m0 = dis*e0, m_{k+1} = dis^2*S)
__device__ __align__(256) __half g_m1[NT * DD];
__device__ __align__(256) __half g_m2[NT * DD];
__device__ __align__(256) float  g_dis[NT];       // d^{-1/2}
__device__ __align__(256) float  g_dsq[NT];       // d^{+1/2}  (0 if deg==0)
__device__ __align__(256) int    g_deg[NT];
__device__ __align__(256) int    g_rowptr[NT + 1]; // partial; final = rowptr[r]+bsum[r>>10]
__device__ __align__(256) int    g_bsum[NBLK_SCAN];
__device__ __align__(256) unsigned short g_pos[EE]; // per-edge within-row index (from hist)
__device__ __align__(256) int    g_col[EE];       // CSR columns

__device__ __forceinline__ int rp(int r) {        // final rowptr
    return g_rowptr[r] + __ldg(&g_bsum[r >> 10]);
}

__device__ __forceinline__ int2 pack_half4(float4 s) {
    __half2 p0 = __floats2half2_rn(s.x, s.y);
    __half2 p1 = __floats2half2_rn(s.z, s.w);
    return make_int2(*reinterpret_cast<int*>(&p0), *reinterpret_cast<int*>(&p1));
}

// histogram of edge rows, 8 edges/thread; records each edge's within-row slot
__global__ void __launch_bounds__(256) k_hist(const int4* __restrict__ row4) {
    int i = (blockIdx.x * blockDim.x + threadIdx.x) * 2;   // int4 index (even)
    if (i < EE / 4) {
        int4 r0 = __ldg(&row4[i]);
        int4 r1 = __ldg(&row4[i + 1]);
        unsigned p0 = atomicAdd(&g_deg[r0.x], 1);
        unsigned p1 = atomicAdd(&g_deg[r0.y], 1);
        unsigned p2 = atomicAdd(&g_deg[r0.z], 1);
        unsigned p3 = atomicAdd(&g_deg[r0.w], 1);
        unsigned p4 = atomicAdd(&g_deg[r1.x], 1);
        unsigned p5 = atomicAdd(&g_deg[r1.y], 1);
        unsigned p6 = atomicAdd(&g_deg[r1.z], 1);
        unsigned p7 = atomicAdd(&g_deg[r1.w], 1);
        uint4 pk;
        pk.x = (p0 & 0xFFFF) | (p1 << 16);
        pk.y = (p2 & 0xFFFF) | (p3 << 16);
        pk.z = (p4 & 0xFFFF) | (p5 << 16);
        pk.w = (p6 & 0xFFFF) | (p7 << 16);
        *reinterpret_cast<uint4*>(&g_pos[i * 4]) = pk;     // 16B aligned: i even
    }
}

// scan step 1 + compute dis/dsq; writes blockwise-exclusive rowptr
__global__ void k_scan1() {
    __shared__ int sh[SCAN_B];
    int i = blockIdx.x * SCAN_B + threadIdx.x;
    int v = (i < NT) ? g_deg[i] : 0;
    if (i < NT) {
        g_dis[i] = (v > 0) ? rsqrtf((float)v) : 0.0f;
        g_dsq[i] = (v > 0) ? sqrtf((float)v)  : 0.0f;
    }
    sh[threadIdx.x] = v;
    __syncthreads();
    for (int off = 1; off < SCAN_B; off <<= 1) {
        int x = (threadIdx.x >= off) ? sh[threadIdx.x - off] : 0;
        __syncthreads();
        sh[threadIdx.x] += x;
        __syncthreads();
    }
    int incl = sh[threadIdx.x];
    if (i < NT) g_rowptr[i] = incl - v;
    if (threadIdx.x == SCAN_B - 1) g_bsum[blockIdx.x] = incl;
}

// exclusive scan of the 147 block sums; patch rowptr[NT] so rp(NT)==EE
__global__ void k_scan2() {
    __shared__ int sh[256];
    int t = threadIdx.x;
    int v = (t < NBLK_SCAN) ? g_bsum[t] : 0;
    sh[t] = v;
    __syncthreads();
    for (int off = 1; off < 256; off <<= 1) {
        int x = (t >= off) ? sh[t - off] : 0;
        __syncthreads();
        sh[t] += x;
        __syncthreads();
    }
    if (t < NBLK_SCAN) {
        int excl = sh[t] - v;
        g_bsum[t] = excl;
        if (t == NBLK_SCAN - 1) g_rowptr[NT] = EE - excl;   // NT>>10 == NBLK_SCAN-1
    }
}

// Fused atomic-FREE CSR fill + m0-init, roles interleaved (3 fill : 7 init)
// so latency-bound fill overlaps DRAM-bound init in every wave.
__global__ void __launch_bounds__(256) k_fill_init(
        const int4* __restrict__ row4, const int4* __restrict__ col4,
        const float4* __restrict__ users, const float4* __restrict__ items) {
    int b = blockIdx.x;
    int g = b / 10;
    int k = b % 10;
    if (k < 3) {
        // ---- fill role: 4 edges/thread ----
        int fb = g * 3 + k;
        if (fb >= FILL_BLOCKS) return;
        int i = fb * blockDim.x + threadIdx.x;             // int4 index
        if (i < EE / 4) {
            int4 r = __ldg(&row4[i]);
            int4 c = __ldg(&col4[i]);
            uint2 pk = *reinterpret_cast<const uint2*>(&g_pos[i * 4]);
            int p0 = rp(r.x) + (pk.x & 0xFFFF);
            int p1 = rp(r.y) + (pk.x >> 16);
            int p2 = rp(r.z) + (pk.y & 0xFFFF);
            int p3 = rp(r.w) + (pk.y >> 16);
            g_col[p0] = c.x;
            g_col[p1] = c.y;
            g_col[p2] = c.z;
            g_col[p3] = c.w;
        }
    } else {
        // ---- init role ----
        int ib = g * 7 + (k - 3);
        if (ib >= INIT_BLOCKS) return;
        int i = ib * blockDim.x + threadIdx.x;             // over NT*16
        if (i < NT * 16) {
            int node = i >> 4;
            float d = g_dis[node];
            float4 x = (node < NU) ? __ldg(&users[i])
                                   : __ldg(&items[i - NU * 16]);
            reinterpret_cast<int2*>(g_m0)[i] =
                pack_half4(make_float4(d * x.x, d * x.y, d * x.z, d * x.w));
        }
    }
}

// CSR SpMM: 16 threads/row, int2 (8B) per lane; unweighted segment-sum of
// scaled fp16 mirrors. Stores next scaled mirror: m_{k+1} = dis[r]^2 * S.
__global__ void __launch_bounds__(256) k_spmm(int hop) {
    int t = blockIdx.x * blockDim.x + threadIdx.x;
    int r = t >> 4;
    if (r >= NT) return;
    int lane = t & 15;

    const int2* __restrict__ srcm = (hop == 0) ? (const int2*)g_m0 : (const int2*)g_m1;
    int2* dstm                    = (hop == 0) ? (int2*)g_m1       : (int2*)g_m2;

    int beg = rp(r);
    int end = rp(r + 1);
    const int* __restrict__ col = g_col;

    float4 s = make_float4(0.f, 0.f, 0.f, 0.f);
    int i = beg;
    for (; i + 3 < end; i += 4) {
        int c0 = __ldg(&col[i]);
        int c1 = __ldg(&col[i + 1]);
        int c2 = __ldg(&col[i + 2]);
        int c3 = __ldg(&col[i + 3]);
        int2 u0 = __ldg(&srcm[c0 * 16 + lane]);
        int2 u1 = __ldg(&srcm[c1 * 16 + lane]);
        int2 u2 = __ldg(&srcm[c2 * 16 + lane]);
        int2 u3 = __ldg(&srcm[c3 * 16 + lane]);
        float2 a0 = __half22float2(*reinterpret_cast<__half2*>(&u0.x));
        float2 b0 = __half22float2(*reinterpret_cast<__half2*>(&u0.y));
        float2 a1 = __half22float2(*reinterpret_cast<__half2*>(&u1.x));
        float2 b1 = __half22float2(*reinterpret_cast<__half2*>(&u1.y));
        float2 a2 = __half22float2(*reinterpret_cast<__half2*>(&u2.x));
        float2 b2 = __half22float2(*reinterpret_cast<__half2*>(&u2.y));
        float2 a3 = __half22float2(*reinterpret_cast<__half2*>(&u3.x));
        float2 b3 = __half22float2(*reinterpret_cast<__half2*>(&u3.y));
        s.x += (a0.x + a1.x) + (a2.x + a3.x);
        s.y += (a0.y + a1.y) + (a2.y + a3.y);
        s.z += (b0.x + b1.x) + (b2.x + b3.x);
        s.w += (b0.y + b1.y) + (b2.y + b3.y);
    }
    for (; i < end; i++) {
        int c = __ldg(&col[i]);
        int2 u = __ldg(&srcm[c * 16 + lane]);
        float2 a = __half22float2(*reinterpret_cast<__half2*>(&u.x));
        float2 b = __half22float2(*reinterpret_cast<__half2*>(&u.y));
        s.x += a.x; s.y += a.y; s.z += b.x; s.w += b.y;
    }

    float dr = g_dis[r];
    float f = dr * dr;
    dstm[r * 16 + lane] =
        pack_half4(make_float4(f * s.x, f * s.y, f * s.z, f * s.w));
}

// Fused hop-3 + gather: one warp per output slot (b, side).
// S = sum_{c in N(r)} m2[c];  out = 0.25*(e0[r] + dsq*(m1[r]+m2[r]) + dis[r]*S)
__global__ void __launch_bounds__(256) k_gather_fused(
        const float* __restrict__ users, const float* __restrict__ items,
        const int* __restrict__ uid, const int* __restrict__ iid,
        float2* __restrict__ out) {
    int t = blockIdx.x * blockDim.x + threadIdx.x;
    int slot = t >> 5;                 // 8192 slots
    if (slot >= BB * 2) return;
    int lane = t & 31;
    int b = slot >> 1, side = slot & 1;

    int node;
    const float2* e0;
    if (!side) { int u = __ldg(&uid[b]); node = u;      e0 = (const float2*)users + u * 32; }
    else       { int v = __ldg(&iid[b]); node = NU + v; e0 = (const float2*)items + v * 32; }

    int beg = rp(node);
    int end = rp(node + 1);
    const int* __restrict__ col = g_col;
    const __half2* __restrict__ m2h = (const __half2*)g_m2;

    float2 S = make_float2(0.f, 0.f);
    int i = beg;
    for (; i + 3 < end; i += 4) {
        int c0 = __ldg(&col[i]);
        int c1 = __ldg(&col[i + 1]);
        int c2 = __ldg(&col[i + 2]);
        int c3 = __ldg(&col[i + 3]);
        float2 x0 = __half22float2(__ldg(&m2h[c0 * 32 + lane]));
        float2 x1 = __half22float2(__ldg(&m2h[c1 * 32 + lane]));
        float2 x2 = __half22float2(__ldg(&m2h[c2 * 32 + lane]));
        float2 x3 = __half22float2(__ldg(&m2h[c3 * 32 + lane]));
        S.x += (x0.x + x1.x) + (x2.x + x3.x);
        S.y += (x0.y + x1.y) + (x2.y + x3.y);
    }
    for (; i < end; i++) {
        int c = __ldg(&col[i]);
        float2 x = __half22float2(__ldg(&m2h[c * 32 + lane]));
        S.x += x.x; S.y += x.y;
    }

    float dr = g_dis[node];
    float dq = g_dsq[node];
    float2 v0 = __ldg(&e0[lane]);
    float2 a1 = __half22float2(((const __half2*)g_m1)[node * 32 + lane]);
    float2 a2 = __half22float2(((const __half2*)g_m2)[node * 32 + lane]);

    float2 o;
    o.x = 0.25f * (v0.x + dq * (a1.x + a2.x) + dr * S.x);
    o.y = 0.25f * (v0.y + dq * (a1.y + a2.y) + dr * S.y);
    out[slot * 32 + lane] = o;         // = b*64 + side*32 + lane
}

extern "C" void kernel_launch(void* const* d_in, const int* in_sizes, int n_in,
                              void* d_out, int out_size) {
    const float* users = (const float*)d_in[0];
    const float* items = (const float*)d_in[1];
    const int*   erow  = (const int*)d_in[2];
    const int*   ecol  = (const int*)d_in[3];
    const int*   uid   = (const int*)d_in[4];
    const int*   iid   = (const int*)d_in[5];
    float2*      out   = (float2*)d_out;

    void* degp = nullptr;
    cudaGetSymbolAddress(&degp, g_deg);
    cudaMemsetAsync(degp, 0, NT * sizeof(int));

    k_hist  <<<HIST_BLOCKS, TB>>>((const int4*)erow);
    k_scan1 <<<NBLK_SCAN, SCAN_B>>>();
    k_scan2 <<<1, 256>>>();
    k_fill_init<<<MIX_BLOCKS, TB>>>(
        (const int4*)erow, (const int4*)ecol,
        (const float4*)users, (const float4*)items);

    int spmm_threads = NT * 16;
    k_spmm<<<(spmm_threads + TB - 1) / TB, TB>>>(0);
    k_spmm<<<(spmm_threads + TB - 1) / TB, TB>>>(1);

    k_gather_fused<<<(BB * 2 * 32 + TB - 1) / TB, TB>>>(users, items, uid, iid, out);
}